// round 5
// baseline (speedup 1.0000x reference)
#include <cuda_runtime.h>
#include <cstdint>
#include <cstddef>

// Problem constants
static constexpr int Bn = 4;
static constexpr int Sn = 2048;
static constexpr int En = 1024;
static constexpr int Hn = 16;
static constexpr int Dn = 64;

// Scratch (device globals; no cudaMalloc allowed)
__device__ float g_qkv[(size_t)Bn * Sn * 3 * En];   // [B,S,3E]
__device__ float g_attn[(size_t)Bn * Sn * En];      // [B,S,E]

__device__ __forceinline__ float tf32_rna(float x) {
    uint32_t u;
    asm("cvt.rna.tf32.f32 %0, %1;" : "=r"(u) : "f"(x));
    return __uint_as_float(u);
}

// Warp-level tf32 MMA: D(16x8) += A(16x8) * B(8x8), fp32 accumulate.
__device__ __forceinline__ void mma_tf32(float* c, const uint32_t* a, const uint32_t* b) {
    asm volatile(
        "mma.sync.aligned.m16n8k8.row.col.f32.tf32.tf32.f32 "
        "{%0,%1,%2,%3}, {%4,%5,%6,%7}, {%8,%9}, {%0,%1,%2,%3};"
        : "+f"(c[0]), "+f"(c[1]), "+f"(c[2]), "+f"(c[3])
        : "r"(a[0]), "r"(a[1]), "r"(a[2]), "r"(a[3]), "r"(b[0]), "r"(b[1]));
}

// ============================================================================
// 2-pass TF32 tensor-core GEMM: C[M,N] = A[M,K] @ Bw[N,K]^T + bias[N]
// A split hi/lo (exact), Bw truncated to tf32 hi (weights; unbiased ~2^-12).
// 128x128 tile, BK=32, double-buffered smem, 256 threads (8 warps).
// ============================================================================
static constexpr int GBM = 128, GBN = 128, GBK = 32;
static constexpr int PAD = 36;
static constexpr int TILE_F = GBM * PAD;
static constexpr int STAGE_F = 3 * TILE_F;           // Ahi, Alo, Bhi
static constexpr int GEMM_SMEM = 2 * STAGE_F * 4;    // 110592 bytes

#define SM_AH(st, r, c) sm[(st) * STAGE_F + 0 * TILE_F + (r) * PAD + (c)]
#define SM_AL(st, r, c) sm[(st) * STAGE_F + 1 * TILE_F + (r) * PAD + (c)]
#define SM_BH(st, r, c) sm[(st) * STAGE_F + 2 * TILE_F + (r) * PAD + (c)]

__global__ __launch_bounds__(256, 1) void gemm_mma_tf32(
    const float* __restrict__ A, const float* __restrict__ Bw,
    const float* __restrict__ bias, float* __restrict__ C,
    int M, int N, int K)
{
    extern __shared__ float sm[];
    const int tid = threadIdx.x;
    const int wid = tid >> 5;
    const int lane = tid & 31;
    const int g = lane >> 2;
    const int t4 = lane & 3;
    const int wm = wid >> 1;
    const int wn = wid & 1;
    const int bm = blockIdx.y * GBM;
    const int bn = blockIdx.x * GBN;
    const int kT = K / GBK;

    float acc[2][8][4];
#pragma unroll
    for (int mt = 0; mt < 2; mt++)
#pragma unroll
        for (int nt = 0; nt < 8; nt++)
#pragma unroll
            for (int i = 0; i < 4; i++) acc[mt][nt][i] = 0.f;

    const int lrow = tid >> 3;
    const int lq = tid & 7;

    float4 pa[4], pb[4];

#pragma unroll
    for (int s = 0; s < 4; s++) {
        const int row = lrow + s * 32;
        pa[s] = *(const float4*)(A + (size_t)(bm + row) * K + lq * 4);
        pb[s] = *(const float4*)(Bw + (size_t)(bn + row) * K + lq * 4);
    }
#pragma unroll
    for (int s = 0; s < 4; s++) {
        const int row = lrow + s * 32;
        float4 v = pa[s];
        float4 hi, lo;
        hi.x = tf32_rna(v.x); lo.x = tf32_rna(v.x - hi.x);
        hi.y = tf32_rna(v.y); lo.y = tf32_rna(v.y - hi.y);
        hi.z = tf32_rna(v.z); lo.z = tf32_rna(v.z - hi.z);
        hi.w = tf32_rna(v.w); lo.w = tf32_rna(v.w - hi.w);
        *(float4*)&SM_AH(0, row, lq * 4) = hi;
        *(float4*)&SM_AL(0, row, lq * 4) = lo;
        v = pb[s];
        hi.x = tf32_rna(v.x); hi.y = tf32_rna(v.y);
        hi.z = tf32_rna(v.z); hi.w = tf32_rna(v.w);
        *(float4*)&SM_BH(0, row, lq * 4) = hi;
    }
    __syncthreads();

    for (int j = 0; j < kT; j++) {
        const int st = j & 1;
        if (j + 1 < kT) {
            const int k0 = (j + 1) * GBK;
#pragma unroll
            for (int s = 0; s < 4; s++) {
                const int row = lrow + s * 32;
                pa[s] = *(const float4*)(A + (size_t)(bm + row) * K + k0 + lq * 4);
                pb[s] = *(const float4*)(Bw + (size_t)(bn + row) * K + k0 + lq * 4);
            }
        }

#pragma unroll
        for (int kb = 0; kb < GBK; kb += 8) {
            uint32_t ah[2][4], al[2][4];
#pragma unroll
            for (int mt = 0; mt < 2; mt++) {
                const int r = wm * 32 + mt * 16 + g;
                ah[mt][0] = __float_as_uint(SM_AH(st, r,     kb + t4));
                ah[mt][1] = __float_as_uint(SM_AH(st, r + 8, kb + t4));
                ah[mt][2] = __float_as_uint(SM_AH(st, r,     kb + t4 + 4));
                ah[mt][3] = __float_as_uint(SM_AH(st, r + 8, kb + t4 + 4));
                al[mt][0] = __float_as_uint(SM_AL(st, r,     kb + t4));
                al[mt][1] = __float_as_uint(SM_AL(st, r + 8, kb + t4));
                al[mt][2] = __float_as_uint(SM_AL(st, r,     kb + t4 + 4));
                al[mt][3] = __float_as_uint(SM_AL(st, r + 8, kb + t4 + 4));
            }
            uint32_t bh[8][2];
#pragma unroll
            for (int nt = 0; nt < 8; nt++) {
                const int c = wn * 64 + nt * 8 + g;
                bh[nt][0] = __float_as_uint(SM_BH(st, c, kb + t4));
                bh[nt][1] = __float_as_uint(SM_BH(st, c, kb + t4 + 4));
            }
#pragma unroll
            for (int mt = 0; mt < 2; mt++)
#pragma unroll
                for (int nt = 0; nt < 8; nt++) {
                    mma_tf32(acc[mt][nt], ah[mt], bh[nt]);
                    mma_tf32(acc[mt][nt], al[mt], bh[nt]);
                }
        }

        if (j + 1 < kT) {
            const int so = st ^ 1;
#pragma unroll
            for (int s = 0; s < 4; s++) {
                const int row = lrow + s * 32;
                float4 v = pa[s];
                float4 hi, lo;
                hi.x = tf32_rna(v.x); lo.x = tf32_rna(v.x - hi.x);
                hi.y = tf32_rna(v.y); lo.y = tf32_rna(v.y - hi.y);
                hi.z = tf32_rna(v.z); lo.z = tf32_rna(v.z - hi.z);
                hi.w = tf32_rna(v.w); lo.w = tf32_rna(v.w - hi.w);
                *(float4*)&SM_AH(so, row, lq * 4) = hi;
                *(float4*)&SM_AL(so, row, lq * 4) = lo;
                v = pb[s];
                hi.x = tf32_rna(v.x); hi.y = tf32_rna(v.y);
                hi.z = tf32_rna(v.z); hi.w = tf32_rna(v.w);
                *(float4*)&SM_BH(so, row, lq * 4) = hi;
            }
        }
        __syncthreads();
    }

#pragma unroll
    for (int mt = 0; mt < 2; mt++) {
        const int r0 = bm + wm * 32 + mt * 16 + g;
#pragma unroll
        for (int nt = 0; nt < 8; nt++) {
            const int c0 = bn + wn * 64 + nt * 8 + t4 * 2;
            const float b0 = bias[c0];
            const float b1 = bias[c0 + 1];
            float2 v0, v1;
            v0.x = acc[mt][nt][0] + b0; v0.y = acc[mt][nt][1] + b1;
            v1.x = acc[mt][nt][2] + b0; v1.y = acc[mt][nt][3] + b1;
            *(float2*)(C + (size_t)r0 * N + c0) = v0;
            *(float2*)(C + (size_t)(r0 + 8) * N + c0) = v1;
        }
    }
}

// ============================================================================
// Flash attention via tf32 mma.sync. BQ=128, BKV=64, 8 warps x 16 q-rows.
// Q truncated-hi (1/8 scale folded), K hi+lo; P truncated-hi, V hi+lo.
// ============================================================================
static constexpr int ABQ = 128, ABK = 64, APAD = 68;
static constexpr int OFF_QH = 0;                       // 128*68
static constexpr int OFF_KH = OFF_QH + ABQ * APAD;
static constexpr int OFF_KL = OFF_KH + ABK * APAD;
static constexpr int OFF_VH = OFF_KL + ABK * APAD;
static constexpr int OFF_VL = OFF_VH + ABK * APAD;
static constexpr int OFF_PS = OFF_VL + ABK * APAD;     // 8 warps * 16*68
static constexpr int ATTN_SMEM = (OFF_PS + 8 * 16 * APAD) * 4;  // 139264 B

__global__ __launch_bounds__(256, 1) void attn_mma(
    const float* __restrict__ qkv, float* __restrict__ out)
{
    extern __shared__ float sm[];
    const int tid = threadIdx.x;
    const int wid = tid >> 5;
    const int lane = tid & 31;
    const int g = lane >> 2;
    const int t4 = lane & 3;
    const int qi = gridDim.x - 1 - blockIdx.x;   // largest workload first
    const int h = blockIdx.y;
    const int b = blockIdx.z;
    const int q0 = qi * ABQ;
    const size_t rs = (size_t)3 * En;
    const float* qbase = qkv + (size_t)b * Sn * rs + (size_t)h * Dn;
    const float* kbase = qbase + En;
    const float* vbase = qbase + 2 * En;

    // Load Q tile, fold 1/sqrt(D)=0.125 scale, truncate to tf32
    for (int i = tid; i < ABQ * 16; i += 256) {
        const int row = i >> 4, c4 = (i & 15) * 4;
        float4 v = *(const float4*)(qbase + (size_t)(q0 + row) * rs + c4);
        float4 hi;
        hi.x = tf32_rna(v.x * 0.125f);
        hi.y = tf32_rna(v.y * 0.125f);
        hi.z = tf32_rna(v.z * 0.125f);
        hi.w = tf32_rna(v.w * 0.125f);
        *(float4*)&sm[OFF_QH + row * APAD + c4] = hi;
    }

    float m0 = -1e30f, m1 = -1e30f, l0 = 0.f, l1 = 0.f;
    float o[8][4];
#pragma unroll
    for (int nt = 0; nt < 8; nt++)
#pragma unroll
        for (int i = 0; i < 4; i++) o[nt][i] = 0.f;

    const int wrow = wid * 16;
    float* Pw = sm + OFF_PS + wid * (16 * APAD);
    const int ntiles = 2 * qi + 2;

    for (int jt = 0; jt < ntiles; jt++) {
        const int k0 = jt * ABK;
        __syncthreads();
        // Load K (hi+lo) and V (hi+lo)
        for (int i = tid; i < ABK * 16; i += 256) {
            const int row = i >> 4, c4 = (i & 15) * 4;
            float4 kv = *(const float4*)(kbase + (size_t)(k0 + row) * rs + c4);
            float4 hi, lo;
            hi.x = tf32_rna(kv.x); lo.x = tf32_rna(kv.x - hi.x);
            hi.y = tf32_rna(kv.y); lo.y = tf32_rna(kv.y - hi.y);
            hi.z = tf32_rna(kv.z); lo.z = tf32_rna(kv.z - hi.z);
            hi.w = tf32_rna(kv.w); lo.w = tf32_rna(kv.w - hi.w);
            *(float4*)&sm[OFF_KH + row * APAD + c4] = hi;
            *(float4*)&sm[OFF_KL + row * APAD + c4] = lo;
            float4 vv = *(const float4*)(vbase + (size_t)(k0 + row) * rs + c4);
            hi.x = tf32_rna(vv.x); lo.x = tf32_rna(vv.x - hi.x);
            hi.y = tf32_rna(vv.y); lo.y = tf32_rna(vv.y - hi.y);
            hi.z = tf32_rna(vv.z); lo.z = tf32_rna(vv.z - hi.z);
            hi.w = tf32_rna(vv.w); lo.w = tf32_rna(vv.w - hi.w);
            *(float4*)&sm[OFF_VH + row * APAD + c4] = hi;
            *(float4*)&sm[OFF_VL + row * APAD + c4] = lo;
        }
        __syncthreads();

        // S = (Q/8) @ K^T, 2-pass (K hi + K lo)
        float acc[8][4];
#pragma unroll
        for (int nt = 0; nt < 8; nt++)
#pragma unroll
            for (int i = 0; i < 4; i++) acc[nt][i] = 0.f;

#pragma unroll
        for (int kb = 0; kb < 8; kb++) {
            uint32_t aq[4];
            aq[0] = __float_as_uint(sm[OFF_QH + (wrow + g) * APAD + kb * 8 + t4]);
            aq[1] = __float_as_uint(sm[OFF_QH + (wrow + g + 8) * APAD + kb * 8 + t4]);
            aq[2] = __float_as_uint(sm[OFF_QH + (wrow + g) * APAD + kb * 8 + t4 + 4]);
            aq[3] = __float_as_uint(sm[OFF_QH + (wrow + g + 8) * APAD + kb * 8 + t4 + 4]);
#pragma unroll
            for (int nt = 0; nt < 8; nt++) {
                uint32_t bh[2], bl[2];
                bh[0] = __float_as_uint(sm[OFF_KH + (nt * 8 + g) * APAD + kb * 8 + t4]);
                bh[1] = __float_as_uint(sm[OFF_KH + (nt * 8 + g) * APAD + kb * 8 + t4 + 4]);
                bl[0] = __float_as_uint(sm[OFF_KL + (nt * 8 + g) * APAD + kb * 8 + t4]);
                bl[1] = __float_as_uint(sm[OFF_KL + (nt * 8 + g) * APAD + kb * 8 + t4 + 4]);
                mma_tf32(acc[nt], aq, bh);
                mma_tf32(acc[nt], aq, bl);
            }
        }

        // Causal mask (only the two diagonal-overlapping tiles need it)
        if (jt >= ntiles - 2) {
            const int r0g = q0 + wrow + g;
            const int r1g = r0g + 8;
#pragma unroll
            for (int nt = 0; nt < 8; nt++) {
                const int c = k0 + nt * 8 + t4 * 2;
                if (c > r0g)     acc[nt][0] = -1e30f;
                if (c + 1 > r0g) acc[nt][1] = -1e30f;
                if (c > r1g)     acc[nt][2] = -1e30f;
                if (c + 1 > r1g) acc[nt][3] = -1e30f;
            }
        }

        // Online softmax (rows g and g+8; reduce across t4 quad)
        float mx0 = -1e30f, mx1 = -1e30f;
#pragma unroll
        for (int nt = 0; nt < 8; nt++) {
            mx0 = fmaxf(mx0, fmaxf(acc[nt][0], acc[nt][1]));
            mx1 = fmaxf(mx1, fmaxf(acc[nt][2], acc[nt][3]));
        }
        mx0 = fmaxf(mx0, __shfl_xor_sync(0xffffffffu, mx0, 1));
        mx0 = fmaxf(mx0, __shfl_xor_sync(0xffffffffu, mx0, 2));
        mx1 = fmaxf(mx1, __shfl_xor_sync(0xffffffffu, mx1, 1));
        mx1 = fmaxf(mx1, __shfl_xor_sync(0xffffffffu, mx1, 2));
        const float mn0 = fmaxf(m0, mx0);
        const float mn1 = fmaxf(m1, mx1);
        const float a0 = __expf(m0 - mn0);
        const float a1 = __expf(m1 - mn1);
        m0 = mn0; m1 = mn1;
        float s0 = 0.f, s1 = 0.f;
#pragma unroll
        for (int nt = 0; nt < 8; nt++) {
            acc[nt][0] = __expf(acc[nt][0] - m0); s0 += acc[nt][0];
            acc[nt][1] = __expf(acc[nt][1] - m0); s0 += acc[nt][1];
            acc[nt][2] = __expf(acc[nt][2] - m1); s1 += acc[nt][2];
            acc[nt][3] = __expf(acc[nt][3] - m1); s1 += acc[nt][3];
        }
        s0 += __shfl_xor_sync(0xffffffffu, s0, 1);
        s0 += __shfl_xor_sync(0xffffffffu, s0, 2);
        s1 += __shfl_xor_sync(0xffffffffu, s1, 1);
        s1 += __shfl_xor_sync(0xffffffffu, s1, 2);
        l0 = l0 * a0 + s0;
        l1 = l1 * a1 + s1;

        // P -> warp-private smem (tf32-truncated), re-layout for A fragment
#pragma unroll
        for (int nt = 0; nt < 8; nt++) {
            Pw[g * APAD + nt * 8 + t4 * 2]           = tf32_rna(acc[nt][0]);
            Pw[g * APAD + nt * 8 + t4 * 2 + 1]       = tf32_rna(acc[nt][1]);
            Pw[(g + 8) * APAD + nt * 8 + t4 * 2]     = tf32_rna(acc[nt][2]);
            Pw[(g + 8) * APAD + nt * 8 + t4 * 2 + 1] = tf32_rna(acc[nt][3]);
        }
        __syncwarp();

        // Rescale O by alpha
#pragma unroll
        for (int nt = 0; nt < 8; nt++) {
            o[nt][0] *= a0; o[nt][1] *= a0;
            o[nt][2] *= a1; o[nt][3] *= a1;
        }

        // O += P @ V, 2-pass (V hi + V lo)
#pragma unroll
        for (int kb = 0; kb < 8; kb++) {
            uint32_t ap[4];
            ap[0] = __float_as_uint(Pw[g * APAD + kb * 8 + t4]);
            ap[1] = __float_as_uint(Pw[(g + 8) * APAD + kb * 8 + t4]);
            ap[2] = __float_as_uint(Pw[g * APAD + kb * 8 + t4 + 4]);
            ap[3] = __float_as_uint(Pw[(g + 8) * APAD + kb * 8 + t4 + 4]);
#pragma unroll
            for (int nt = 0; nt < 8; nt++) {
                uint32_t bh[2], bl[2];
                bh[0] = __float_as_uint(sm[OFF_VH + (kb * 8 + t4) * APAD + nt * 8 + g]);
                bh[1] = __float_as_uint(sm[OFF_VH + (kb * 8 + t4 + 4) * APAD + nt * 8 + g]);
                bl[0] = __float_as_uint(sm[OFF_VL + (kb * 8 + t4) * APAD + nt * 8 + g]);
                bl[1] = __float_as_uint(sm[OFF_VL + (kb * 8 + t4 + 4) * APAD + nt * 8 + g]);
                mma_tf32(o[nt], ap, bh);
                mma_tf32(o[nt], ap, bl);
            }
        }
        __syncwarp();
    }

    // Normalize and write out[b, row, h*D + col]
    const float i0 = 1.f / l0;
    const float i1 = 1.f / l1;
    const int r0g = q0 + wrow + g;
#pragma unroll
    for (int nt = 0; nt < 8; nt++) {
        const int col = h * Dn + nt * 8 + t4 * 2;
        float2 v0, v1;
        v0.x = o[nt][0] * i0; v0.y = o[nt][1] * i0;
        v1.x = o[nt][2] * i1; v1.y = o[nt][3] * i1;
        *(float2*)(out + ((size_t)b * Sn + r0g) * En + col) = v0;
        *(float2*)(out + ((size_t)b * Sn + r0g + 8) * En + col) = v1;
    }
}

// ----------------------------------------------------------------------------
extern "C" void kernel_launch(void* const* d_in, const int* in_sizes, int n_in,
                              void* d_out, int out_size)
{
    const float* x     = (const float*)d_in[0];
    const float* w_in  = (const float*)d_in[1];
    const float* b_in  = (const float*)d_in[2];
    const float* w_out = (const float*)d_in[3];
    const float* b_out = (const float*)d_in[4];
    float* out = (float*)d_out;

    float* qkv = nullptr;
    float* attn = nullptr;
    cudaGetSymbolAddress((void**)&qkv, g_qkv);
    cudaGetSymbolAddress((void**)&attn, g_attn);

    const int M = Bn * Sn;  // 8192

    static bool attr_set = false;
    if (!attr_set) {
        cudaFuncSetAttribute(gemm_mma_tf32, cudaFuncAttributeMaxDynamicSharedMemorySize,
                             GEMM_SMEM);
        cudaFuncSetAttribute(attn_mma, cudaFuncAttributeMaxDynamicSharedMemorySize,
                             ATTN_SMEM);
        attr_set = true;
    }

    // 1) QKV projection (2-pass tf32 tensor cores)
    {
        dim3 grid((3 * En) / GBN, M / GBM);
        gemm_mma_tf32<<<grid, 256, GEMM_SMEM>>>(x, w_in, b_in, qkv, M, 3 * En, En);
    }

    // 2) Causal flash attention (tf32 tensor cores)
    {
        dim3 grid(Sn / ABQ, Hn, Bn);
        attn_mma<<<grid, 256, ATTN_SMEM>>>(qkv, attn);
    }

    // 3) Output projection (2-pass tf32 tensor cores)
    {
        dim3 grid(En / GBN, M / GBM);
        gemm_mma_tf32<<<grid, 256, GEMM_SMEM>>>(attn, w_out, b_out, out, M, En, En);
    }
}

// round 6
// speedup vs baseline: 1.6333x; 1.6333x over previous
#include <cuda_runtime.h>
#include <cstdint>
#include <cstddef>

// Problem constants
static constexpr int Bn = 4;
static constexpr int Sn = 2048;
static constexpr int En = 1024;
static constexpr int Hn = 16;
static constexpr int Dn = 64;

// Scratch (device globals; no cudaMalloc allowed)
__device__ float g_qkv[(size_t)Bn * Sn * 3 * En];   // [B,S,3E]
__device__ float g_attn[(size_t)Bn * Sn * En];      // [B,S,E]

__device__ __forceinline__ float tf32_rna(float x) {
    uint32_t u;
    asm("cvt.rna.tf32.f32 %0, %1;" : "=r"(u) : "f"(x));
    return __uint_as_float(u);
}

// Warp-level tf32 MMA: D(16x8) += A(16x8) * B(8x8), fp32 accumulate.
__device__ __forceinline__ void mma_tf32(float* c, const uint32_t* a, const uint32_t* b) {
    asm volatile(
        "mma.sync.aligned.m16n8k8.row.col.f32.tf32.tf32.f32 "
        "{%0,%1,%2,%3}, {%4,%5,%6,%7}, {%8,%9}, {%0,%1,%2,%3};"
        : "+f"(c[0]), "+f"(c[1]), "+f"(c[2]), "+f"(c[3])
        : "r"(a[0]), "r"(a[1]), "r"(a[2]), "r"(a[3]), "r"(b[0]), "r"(b[1]));
}

// ============================================================================
// 3xTF32 tensor-core GEMM (R4 proven version): C = A @ Bw^T + bias
// 128x128 tile, BK=32, double-buffered smem, 256 threads (8 warps).
// ============================================================================
static constexpr int GBM = 128, GBN = 128, GBK = 32;
static constexpr int PAD = 36;
static constexpr int TILE_F = GBM * PAD;
static constexpr int STAGE_F = 4 * TILE_F;           // Ahi, Alo, Bhi, Blo
static constexpr int GEMM_SMEM = 2 * STAGE_F * 4;    // 147456 bytes

#define SM_AH(st, r, c) sm[(st) * STAGE_F + 0 * TILE_F + (r) * PAD + (c)]
#define SM_AL(st, r, c) sm[(st) * STAGE_F + 1 * TILE_F + (r) * PAD + (c)]
#define SM_BH(st, r, c) sm[(st) * STAGE_F + 2 * TILE_F + (r) * PAD + (c)]
#define SM_BL(st, r, c) sm[(st) * STAGE_F + 3 * TILE_F + (r) * PAD + (c)]

__global__ __launch_bounds__(256, 1) void gemm_mma_tf32(
    const float* __restrict__ A, const float* __restrict__ Bw,
    const float* __restrict__ bias, float* __restrict__ C,
    int M, int N, int K)
{
    extern __shared__ float sm[];
    const int tid = threadIdx.x;
    const int wid = tid >> 5;
    const int lane = tid & 31;
    const int g = lane >> 2;
    const int t4 = lane & 3;
    const int wm = wid >> 1;
    const int wn = wid & 1;
    const int bm = blockIdx.y * GBM;
    const int bn = blockIdx.x * GBN;
    const int kT = K / GBK;

    float acc[2][8][4];
#pragma unroll
    for (int mt = 0; mt < 2; mt++)
#pragma unroll
        for (int nt = 0; nt < 8; nt++)
#pragma unroll
            for (int i = 0; i < 4; i++) acc[mt][nt][i] = 0.f;

    const int lrow = tid >> 3;
    const int lq = tid & 7;

    float4 pa[4], pb[4];

#pragma unroll
    for (int s = 0; s < 4; s++) {
        const int row = lrow + s * 32;
        pa[s] = *(const float4*)(A + (size_t)(bm + row) * K + lq * 4);
        pb[s] = *(const float4*)(Bw + (size_t)(bn + row) * K + lq * 4);
    }
#pragma unroll
    for (int s = 0; s < 4; s++) {
        const int row = lrow + s * 32;
        float4 v = pa[s];
        float4 hi, lo;
        hi.x = tf32_rna(v.x); lo.x = tf32_rna(v.x - hi.x);
        hi.y = tf32_rna(v.y); lo.y = tf32_rna(v.y - hi.y);
        hi.z = tf32_rna(v.z); lo.z = tf32_rna(v.z - hi.z);
        hi.w = tf32_rna(v.w); lo.w = tf32_rna(v.w - hi.w);
        *(float4*)&SM_AH(0, row, lq * 4) = hi;
        *(float4*)&SM_AL(0, row, lq * 4) = lo;
        v = pb[s];
        hi.x = tf32_rna(v.x); lo.x = tf32_rna(v.x - hi.x);
        hi.y = tf32_rna(v.y); lo.y = tf32_rna(v.y - hi.y);
        hi.z = tf32_rna(v.z); lo.z = tf32_rna(v.z - hi.z);
        hi.w = tf32_rna(v.w); lo.w = tf32_rna(v.w - hi.w);
        *(float4*)&SM_BH(0, row, lq * 4) = hi;
        *(float4*)&SM_BL(0, row, lq * 4) = lo;
    }
    __syncthreads();

    for (int j = 0; j < kT; j++) {
        const int st = j & 1;
        if (j + 1 < kT) {
            const int k0 = (j + 1) * GBK;
#pragma unroll
            for (int s = 0; s < 4; s++) {
                const int row = lrow + s * 32;
                pa[s] = *(const float4*)(A + (size_t)(bm + row) * K + k0 + lq * 4);
                pb[s] = *(const float4*)(Bw + (size_t)(bn + row) * K + k0 + lq * 4);
            }
        }

#pragma unroll
        for (int kb = 0; kb < GBK; kb += 8) {
            uint32_t ah[2][4], al[2][4];
#pragma unroll
            for (int mt = 0; mt < 2; mt++) {
                const int r = wm * 32 + mt * 16 + g;
                ah[mt][0] = __float_as_uint(SM_AH(st, r,     kb + t4));
                ah[mt][1] = __float_as_uint(SM_AH(st, r + 8, kb + t4));
                ah[mt][2] = __float_as_uint(SM_AH(st, r,     kb + t4 + 4));
                ah[mt][3] = __float_as_uint(SM_AH(st, r + 8, kb + t4 + 4));
                al[mt][0] = __float_as_uint(SM_AL(st, r,     kb + t4));
                al[mt][1] = __float_as_uint(SM_AL(st, r + 8, kb + t4));
                al[mt][2] = __float_as_uint(SM_AL(st, r,     kb + t4 + 4));
                al[mt][3] = __float_as_uint(SM_AL(st, r + 8, kb + t4 + 4));
            }
            uint32_t bh[8][2], bl[8][2];
#pragma unroll
            for (int nt = 0; nt < 8; nt++) {
                const int c = wn * 64 + nt * 8 + g;
                bh[nt][0] = __float_as_uint(SM_BH(st, c, kb + t4));
                bh[nt][1] = __float_as_uint(SM_BH(st, c, kb + t4 + 4));
                bl[nt][0] = __float_as_uint(SM_BL(st, c, kb + t4));
                bl[nt][1] = __float_as_uint(SM_BL(st, c, kb + t4 + 4));
            }
#pragma unroll
            for (int mt = 0; mt < 2; mt++)
#pragma unroll
                for (int nt = 0; nt < 8; nt++) {
                    mma_tf32(acc[mt][nt], ah[mt], bh[nt]);
                    mma_tf32(acc[mt][nt], ah[mt], bl[nt]);
                    mma_tf32(acc[mt][nt], al[mt], bh[nt]);
                }
        }

        if (j + 1 < kT) {
            const int so = st ^ 1;
#pragma unroll
            for (int s = 0; s < 4; s++) {
                const int row = lrow + s * 32;
                float4 v = pa[s];
                float4 hi, lo;
                hi.x = tf32_rna(v.x); lo.x = tf32_rna(v.x - hi.x);
                hi.y = tf32_rna(v.y); lo.y = tf32_rna(v.y - hi.y);
                hi.z = tf32_rna(v.z); lo.z = tf32_rna(v.z - hi.z);
                hi.w = tf32_rna(v.w); lo.w = tf32_rna(v.w - hi.w);
                *(float4*)&SM_AH(so, row, lq * 4) = hi;
                *(float4*)&SM_AL(so, row, lq * 4) = lo;
                v = pb[s];
                hi.x = tf32_rna(v.x); lo.x = tf32_rna(v.x - hi.x);
                hi.y = tf32_rna(v.y); lo.y = tf32_rna(v.y - hi.y);
                hi.z = tf32_rna(v.z); lo.z = tf32_rna(v.z - hi.z);
                hi.w = tf32_rna(v.w); lo.w = tf32_rna(v.w - hi.w);
                *(float4*)&SM_BH(so, row, lq * 4) = hi;
                *(float4*)&SM_BL(so, row, lq * 4) = lo;
            }
        }
        __syncthreads();
    }

#pragma unroll
    for (int mt = 0; mt < 2; mt++) {
        const int r0 = bm + wm * 32 + mt * 16 + g;
#pragma unroll
        for (int nt = 0; nt < 8; nt++) {
            const int c0 = bn + wn * 64 + nt * 8 + t4 * 2;
            const float b0 = bias[c0];
            const float b1 = bias[c0 + 1];
            float2 v0, v1;
            v0.x = acc[mt][nt][0] + b0; v0.y = acc[mt][nt][1] + b1;
            v1.x = acc[mt][nt][2] + b0; v1.y = acc[mt][nt][3] + b1;
            *(float2*)(C + (size_t)r0 * N + c0) = v0;
            *(float2*)(C + (size_t)(r0 + 8) * N + c0) = v1;
        }
    }
}

// ============================================================================
// Flash attention via tf32 mma.sync. BQ=128, BKV=64, 8 warps x 16 q-rows.
// Single-pass truncated-tf32 operands everywhere (Q,K,P,V hi only).
// smem = 104448 B -> 2 CTAs/SM for latency hiding.
// ============================================================================
static constexpr int ABQ = 128, ABK = 64, APAD = 68;
static constexpr int OFF_QH = 0;                       // 128*68
static constexpr int OFF_KH = OFF_QH + ABQ * APAD;
static constexpr int OFF_VH = OFF_KH + ABK * APAD;
static constexpr int OFF_PS = OFF_VH + ABK * APAD;     // 8 warps * 16*68
static constexpr int ATTN_SMEM = (OFF_PS + 8 * 16 * APAD) * 4;  // 104448 B

__global__ __launch_bounds__(256, 2) void attn_mma(
    const float* __restrict__ qkv, float* __restrict__ out)
{
    extern __shared__ float sm[];
    const int tid = threadIdx.x;
    const int wid = tid >> 5;
    const int lane = tid & 31;
    const int g = lane >> 2;
    const int t4 = lane & 3;
    const int qi = gridDim.x - 1 - blockIdx.x;   // largest workload first
    const int h = blockIdx.y;
    const int b = blockIdx.z;
    const int q0 = qi * ABQ;
    const size_t rs = (size_t)3 * En;
    const float* qbase = qkv + (size_t)b * Sn * rs + (size_t)h * Dn;
    const float* kbase = qbase + En;
    const float* vbase = qbase + 2 * En;

    // Load Q tile, fold 1/sqrt(D)=0.125 scale, truncate to tf32
    for (int i = tid; i < ABQ * 16; i += 256) {
        const int row = i >> 4, c4 = (i & 15) * 4;
        float4 v = *(const float4*)(qbase + (size_t)(q0 + row) * rs + c4);
        float4 hi;
        hi.x = tf32_rna(v.x * 0.125f);
        hi.y = tf32_rna(v.y * 0.125f);
        hi.z = tf32_rna(v.z * 0.125f);
        hi.w = tf32_rna(v.w * 0.125f);
        *(float4*)&sm[OFF_QH + row * APAD + c4] = hi;
    }

    float m0 = -1e30f, m1 = -1e30f, l0 = 0.f, l1 = 0.f;
    float o[8][4];
#pragma unroll
    for (int nt = 0; nt < 8; nt++)
#pragma unroll
        for (int i = 0; i < 4; i++) o[nt][i] = 0.f;

    const int wrow = wid * 16;
    float* Pw = sm + OFF_PS + wid * (16 * APAD);
    const int ntiles = 2 * qi + 2;

    for (int jt = 0; jt < ntiles; jt++) {
        const int k0 = jt * ABK;
        __syncthreads();
        // Load K (hi) and V (hi)
        for (int i = tid; i < ABK * 16; i += 256) {
            const int row = i >> 4, c4 = (i & 15) * 4;
            float4 kv = *(const float4*)(kbase + (size_t)(k0 + row) * rs + c4);
            float4 hi;
            hi.x = tf32_rna(kv.x); hi.y = tf32_rna(kv.y);
            hi.z = tf32_rna(kv.z); hi.w = tf32_rna(kv.w);
            *(float4*)&sm[OFF_KH + row * APAD + c4] = hi;
            float4 vv = *(const float4*)(vbase + (size_t)(k0 + row) * rs + c4);
            hi.x = tf32_rna(vv.x); hi.y = tf32_rna(vv.y);
            hi.z = tf32_rna(vv.z); hi.w = tf32_rna(vv.w);
            *(float4*)&sm[OFF_VH + row * APAD + c4] = hi;
        }
        __syncthreads();

        // S = (Q/8) @ K^T
        float acc[8][4];
#pragma unroll
        for (int nt = 0; nt < 8; nt++)
#pragma unroll
            for (int i = 0; i < 4; i++) acc[nt][i] = 0.f;

#pragma unroll
        for (int kb = 0; kb < 8; kb++) {
            uint32_t aq[4];
            aq[0] = __float_as_uint(sm[OFF_QH + (wrow + g) * APAD + kb * 8 + t4]);
            aq[1] = __float_as_uint(sm[OFF_QH + (wrow + g + 8) * APAD + kb * 8 + t4]);
            aq[2] = __float_as_uint(sm[OFF_QH + (wrow + g) * APAD + kb * 8 + t4 + 4]);
            aq[3] = __float_as_uint(sm[OFF_QH + (wrow + g + 8) * APAD + kb * 8 + t4 + 4]);
#pragma unroll
            for (int nt = 0; nt < 8; nt++) {
                uint32_t bh[2];
                bh[0] = __float_as_uint(sm[OFF_KH + (nt * 8 + g) * APAD + kb * 8 + t4]);
                bh[1] = __float_as_uint(sm[OFF_KH + (nt * 8 + g) * APAD + kb * 8 + t4 + 4]);
                mma_tf32(acc[nt], aq, bh);
            }
        }

        // Causal mask (only the two diagonal-overlapping tiles need it)
        if (jt >= ntiles - 2) {
            const int r0g = q0 + wrow + g;
            const int r1g = r0g + 8;
#pragma unroll
            for (int nt = 0; nt < 8; nt++) {
                const int c = k0 + nt * 8 + t4 * 2;
                if (c > r0g)     acc[nt][0] = -1e30f;
                if (c + 1 > r0g) acc[nt][1] = -1e30f;
                if (c > r1g)     acc[nt][2] = -1e30f;
                if (c + 1 > r1g) acc[nt][3] = -1e30f;
            }
        }

        // Online softmax (rows g and g+8; reduce across t4 quad)
        float mx0 = -1e30f, mx1 = -1e30f;
#pragma unroll
        for (int nt = 0; nt < 8; nt++) {
            mx0 = fmaxf(mx0, fmaxf(acc[nt][0], acc[nt][1]));
            mx1 = fmaxf(mx1, fmaxf(acc[nt][2], acc[nt][3]));
        }
        mx0 = fmaxf(mx0, __shfl_xor_sync(0xffffffffu, mx0, 1));
        mx0 = fmaxf(mx0, __shfl_xor_sync(0xffffffffu, mx0, 2));
        mx1 = fmaxf(mx1, __shfl_xor_sync(0xffffffffu, mx1, 1));
        mx1 = fmaxf(mx1, __shfl_xor_sync(0xffffffffu, mx1, 2));
        const float mn0 = fmaxf(m0, mx0);
        const float mn1 = fmaxf(m1, mx1);
        const float a0 = __expf(m0 - mn0);
        const float a1 = __expf(m1 - mn1);
        m0 = mn0; m1 = mn1;
        float s0 = 0.f, s1 = 0.f;
#pragma unroll
        for (int nt = 0; nt < 8; nt++) {
            acc[nt][0] = __expf(acc[nt][0] - m0); s0 += acc[nt][0];
            acc[nt][1] = __expf(acc[nt][1] - m0); s0 += acc[nt][1];
            acc[nt][2] = __expf(acc[nt][2] - m1); s1 += acc[nt][2];
            acc[nt][3] = __expf(acc[nt][3] - m1); s1 += acc[nt][3];
        }
        s0 += __shfl_xor_sync(0xffffffffu, s0, 1);
        s0 += __shfl_xor_sync(0xffffffffu, s0, 2);
        s1 += __shfl_xor_sync(0xffffffffu, s1, 1);
        s1 += __shfl_xor_sync(0xffffffffu, s1, 2);
        l0 = l0 * a0 + s0;
        l1 = l1 * a1 + s1;

        // P -> warp-private smem (tf32-truncated), re-layout for A fragment
#pragma unroll
        for (int nt = 0; nt < 8; nt++) {
            Pw[g * APAD + nt * 8 + t4 * 2]           = tf32_rna(acc[nt][0]);
            Pw[g * APAD + nt * 8 + t4 * 2 + 1]       = tf32_rna(acc[nt][1]);
            Pw[(g + 8) * APAD + nt * 8 + t4 * 2]     = tf32_rna(acc[nt][2]);
            Pw[(g + 8) * APAD + nt * 8 + t4 * 2 + 1] = tf32_rna(acc[nt][3]);
        }
        __syncwarp();

        // Rescale O by alpha
#pragma unroll
        for (int nt = 0; nt < 8; nt++) {
            o[nt][0] *= a0; o[nt][1] *= a0;
            o[nt][2] *= a1; o[nt][3] *= a1;
        }

        // O += P @ V
#pragma unroll
        for (int kb = 0; kb < 8; kb++) {
            uint32_t ap[4];
            ap[0] = __float_as_uint(Pw[g * APAD + kb * 8 + t4]);
            ap[1] = __float_as_uint(Pw[(g + 8) * APAD + kb * 8 + t4]);
            ap[2] = __float_as_uint(Pw[g * APAD + kb * 8 + t4 + 4]);
            ap[3] = __float_as_uint(Pw[(g + 8) * APAD + kb * 8 + t4 + 4]);
#pragma unroll
            for (int nt = 0; nt < 8; nt++) {
                uint32_t bh[2];
                bh[0] = __float_as_uint(sm[OFF_VH + (kb * 8 + t4) * APAD + nt * 8 + g]);
                bh[1] = __float_as_uint(sm[OFF_VH + (kb * 8 + t4 + 4) * APAD + nt * 8 + g]);
                mma_tf32(o[nt], ap, bh);
            }
        }
        __syncwarp();
    }

    // Normalize and write out[b, row, h*D + col]
    const float i0 = 1.f / l0;
    const float i1 = 1.f / l1;
    const int r0g = q0 + wrow + g;
#pragma unroll
    for (int nt = 0; nt < 8; nt++) {
        const int col = h * Dn + nt * 8 + t4 * 2;
        float2 v0, v1;
        v0.x = o[nt][0] * i0; v0.y = o[nt][1] * i0;
        v1.x = o[nt][2] * i1; v1.y = o[nt][3] * i1;
        *(float2*)(out + ((size_t)b * Sn + r0g) * En + col) = v0;
        *(float2*)(out + ((size_t)b * Sn + r0g + 8) * En + col) = v1;
    }
}

// ----------------------------------------------------------------------------
extern "C" void kernel_launch(void* const* d_in, const int* in_sizes, int n_in,
                              void* d_out, int out_size)
{
    const float* x     = (const float*)d_in[0];
    const float* w_in  = (const float*)d_in[1];
    const float* b_in  = (const float*)d_in[2];
    const float* w_out = (const float*)d_in[3];
    const float* b_out = (const float*)d_in[4];
    float* out = (float*)d_out;

    float* qkv = nullptr;
    float* attn = nullptr;
    cudaGetSymbolAddress((void**)&qkv, g_qkv);
    cudaGetSymbolAddress((void**)&attn, g_attn);

    const int M = Bn * Sn;  // 8192

    static bool attr_set = false;
    if (!attr_set) {
        cudaFuncSetAttribute(gemm_mma_tf32, cudaFuncAttributeMaxDynamicSharedMemorySize,
                             GEMM_SMEM);
        cudaFuncSetAttribute(attn_mma, cudaFuncAttributeMaxDynamicSharedMemorySize,
                             ATTN_SMEM);
        attr_set = true;
    }

    // 1) QKV projection (3-pass tf32 tensor cores)
    {
        dim3 grid((3 * En) / GBN, M / GBM);
        gemm_mma_tf32<<<grid, 256, GEMM_SMEM>>>(x, w_in, b_in, qkv, M, 3 * En, En);
    }

    // 2) Causal flash attention (tf32 tensor cores, 1-pass, 2 CTAs/SM)
    {
        dim3 grid(Sn / ABQ, Hn, Bn);
        attn_mma<<<grid, 256, ATTN_SMEM>>>(qkv, attn);
    }

    // 3) Output projection (3-pass tf32 tensor cores)
    {
        dim3 grid(En / GBN, M / GBM);
        gemm_mma_tf32<<<grid, 256, GEMM_SMEM>>>(attn, w_out, b_out, out, M, En, En);
    }
}

// round 7
// speedup vs baseline: 2.3165x; 1.4183x over previous
#include <cuda_runtime.h>
#include <cuda_bf16.h>
#include <cstdint>
#include <cstddef>

// Problem constants
static constexpr int Bn = 4;
static constexpr int Sn = 2048;
static constexpr int En = 1024;
static constexpr int Hn = 16;
static constexpr int Dn = 64;

// Scratch (device globals; no cudaMalloc allowed)
__device__ float g_qkv[(size_t)Bn * Sn * 3 * En];   // [B,S,3E]
__device__ float g_attn[(size_t)Bn * Sn * En];      // [B,S,E]

__device__ __forceinline__ float tf32_rna(float x) {
    uint32_t u;
    asm("cvt.rna.tf32.f32 %0, %1;" : "=r"(u) : "f"(x));
    return __uint_as_float(u);
}

// Warp-level tf32 MMA (attention): D(16x8) += A(16x8) * B(8x8), fp32 acc.
__device__ __forceinline__ void mma_tf32(float* c, const uint32_t* a, const uint32_t* b) {
    asm volatile(
        "mma.sync.aligned.m16n8k8.row.col.f32.tf32.tf32.f32 "
        "{%0,%1,%2,%3}, {%4,%5,%6,%7}, {%8,%9}, {%0,%1,%2,%3};"
        : "+f"(c[0]), "+f"(c[1]), "+f"(c[2]), "+f"(c[3])
        : "r"(a[0]), "r"(a[1]), "r"(a[2]), "r"(a[3]), "r"(b[0]), "r"(b[1]));
}

// Warp-level bf16 MMA: D(16x8) += A(16x16) * B(16x8), fp32 acc.
__device__ __forceinline__ void mma_bf16(float* c, const uint32_t* a, const uint32_t* b) {
    asm volatile(
        "mma.sync.aligned.m16n8k16.row.col.f32.bf16.bf16.f32 "
        "{%0,%1,%2,%3}, {%4,%5,%6,%7}, {%8,%9}, {%0,%1,%2,%3};"
        : "+f"(c[0]), "+f"(c[1]), "+f"(c[2]), "+f"(c[3])
        : "r"(a[0]), "r"(a[1]), "r"(a[2]), "r"(a[3]), "r"(b[0]), "r"(b[1]));
}

// Split x into bf16 hi + lo, packing pairs (x0 -> low half, x1 -> high half).
__device__ __forceinline__ void split_pack_bf16(float x0, float x1,
                                                uint32_t& hi, uint32_t& lo) {
    __nv_bfloat162 h = __floats2bfloat162_rn(x0, x1);
    float f0 = __bfloat162float(h.x);
    float f1 = __bfloat162float(h.y);
    __nv_bfloat162 l = __floats2bfloat162_rn(x0 - f0, x1 - f1);
    hi = *(uint32_t*)&h;
    lo = *(uint32_t*)&l;
}

// ============================================================================
// 3xBF16 tensor-core GEMM: C[M,N] = A[M,K] @ Bw[N,K]^T + bias[N]
// 128x128 tile, BK=32, double-buffered fragment-major smem, 256 thr, 2 CTA/SM.
// Error: dropped lo*lo term ~2^-18/product -> ~1e-5 total (unbiased).
//
// Fragment-major smem layout (bf16 units), per stage (16384 bf16 = 32KB):
//   AH=0, AL=4096, BH=8192, BL=12288
// A block (16x16): flat = g*32 + t4*8 + khalf*4 + half*2 + klo ; blocks mblk*2+kblk
// B block (8x16):  flat = g*16 + t4*4 + khalf*2 + klo        ; blocks nblk*2+kblk
// ============================================================================
static constexpr int GBM = 128, GBN = 128, GBK = 32;
static constexpr int STAGE_E = 16384;                // bf16 elems per stage
static constexpr int GEMM_SMEM = 2 * STAGE_E * 2;    // 65536 bytes

__global__ __launch_bounds__(256, 2) void gemm_mma_bf16(
    const float* __restrict__ A, const float* __restrict__ Bw,
    const float* __restrict__ bias, float* __restrict__ C,
    int M, int N, int K)
{
    extern __shared__ uint16_t smu[];
    uint32_t* sm32 = (uint32_t*)smu;

    const int tid = threadIdx.x;
    const int wid = tid >> 5;
    const int lane = tid & 31;
    const int g = lane >> 2;
    const int t4 = lane & 3;
    const int wm = wid >> 1;      // 0..3
    const int wn = wid & 1;       // 0..1
    const int bm = blockIdx.y * GBM;
    const int bn = blockIdx.x * GBN;
    const int kT = K / GBK;

    float acc[2][8][4];
#pragma unroll
    for (int mt = 0; mt < 2; mt++)
#pragma unroll
        for (int nt = 0; nt < 8; nt++)
#pragma unroll
            for (int i = 0; i < 4; i++) acc[mt][nt][i] = 0.f;

    // Producer indexing: thread covers rows lrow+32s, k-cols [lq*4, lq*4+4)
    const int lrow = tid >> 3;    // 0..31
    const int lq = tid & 7;
    const int k0l = lq * 4;
    const int kblkL = k0l >> 4;
    const int kcL = k0l & 15;
    const int khalfL = kcL >> 3;
    const int t4L = (kcL & 7) >> 1;   // 0 or 2; writes t4L and t4L+1

    // Per-s write offsets (u32 index within region)
    int aw[4], bw2[4];
#pragma unroll
    for (int s = 0; s < 4; s++) {
        const int row = lrow + s * 32;
        const int mblk = row >> 4, r16 = row & 15;
        const int halfA = r16 >> 3, gA = r16 & 7;
        const int aoff = (mblk * 2 + kblkL) * 256 + gA * 32 + khalfL * 4 + halfA * 2;
        aw[s] = (aoff >> 1) + t4L * 4;   // u32 index; second write at +4
        const int nblk = row >> 3, gB = row & 7;
        const int boff = (nblk * 2 + kblkL) * 128 + gB * 16 + khalfL * 2;
        bw2[s] = (boff >> 1) + t4L * 2;  // u32 index; second write at +2
    }

    float4 pa[4], pb[4];
#pragma unroll
    for (int s = 0; s < 4; s++) {
        const int row = lrow + s * 32;
        pa[s] = *(const float4*)(A + (size_t)(bm + row) * K + k0l);
        pb[s] = *(const float4*)(Bw + (size_t)(bn + row) * K + k0l);
    }

    // store tile 0
    {
        uint32_t* AH = sm32;                     // stage 0
        uint32_t* AL = sm32 + 2048;
        uint32_t* BH = sm32 + 4096;
        uint32_t* BL = sm32 + 6144;
#pragma unroll
        for (int s = 0; s < 4; s++) {
            uint32_t h01, l01, h23, l23;
            split_pack_bf16(pa[s].x, pa[s].y, h01, l01);
            split_pack_bf16(pa[s].z, pa[s].w, h23, l23);
            AH[aw[s]] = h01; AH[aw[s] + 4] = h23;
            AL[aw[s]] = l01; AL[aw[s] + 4] = l23;
            split_pack_bf16(pb[s].x, pb[s].y, h01, l01);
            split_pack_bf16(pb[s].z, pb[s].w, h23, l23);
            BH[bw2[s]] = h01; BH[bw2[s] + 2] = h23;
            BL[bw2[s]] = l01; BL[bw2[s] + 2] = l23;
        }
    }
    __syncthreads();

    for (int j = 0; j < kT; j++) {
        const int st = j & 1;
        if (j + 1 < kT) {
            const int k0 = (j + 1) * GBK + k0l;
#pragma unroll
            for (int s = 0; s < 4; s++) {
                const int row = lrow + s * 32;
                pa[s] = *(const float4*)(A + (size_t)(bm + row) * K + k0);
                pb[s] = *(const float4*)(Bw + (size_t)(bn + row) * K + k0);
            }
        }

        // compute from stage st
        const uint16_t* stg = smu + st * STAGE_E;
#pragma unroll
        for (int kblk = 0; kblk < 2; kblk++) {
            uint4 ahi[2], alo[2];
#pragma unroll
            for (int mt = 0; mt < 2; mt++) {
                const int mblk = wm * 2 + mt;
                const int base = (mblk * 2 + kblk) * 256 + g * 32 + t4 * 8;
                ahi[mt] = *(const uint4*)(stg + base);          // AH region
                alo[mt] = *(const uint4*)(stg + 4096 + base);   // AL region
            }
#pragma unroll
            for (int nt = 0; nt < 8; nt++) {
                const int nblk = wn * 8 + nt;
                const int bbase = (nblk * 2 + kblk) * 128 + g * 16 + t4 * 4;
                uint2 bh = *(const uint2*)(stg + 8192 + bbase);
                uint2 bl = *(const uint2*)(stg + 12288 + bbase);
#pragma unroll
                for (int mt = 0; mt < 2; mt++) {
                    mma_bf16(acc[mt][nt], (const uint32_t*)&ahi[mt], (const uint32_t*)&bh);
                    mma_bf16(acc[mt][nt], (const uint32_t*)&ahi[mt], (const uint32_t*)&bl);
                    mma_bf16(acc[mt][nt], (const uint32_t*)&alo[mt], (const uint32_t*)&bh);
                }
            }
        }

        if (j + 1 < kT) {
            const int so = st ^ 1;
            uint32_t* AH = sm32 + so * (STAGE_E / 2);
            uint32_t* AL = AH + 2048;
            uint32_t* BH = AH + 4096;
            uint32_t* BL = AH + 6144;
#pragma unroll
            for (int s = 0; s < 4; s++) {
                uint32_t h01, l01, h23, l23;
                split_pack_bf16(pa[s].x, pa[s].y, h01, l01);
                split_pack_bf16(pa[s].z, pa[s].w, h23, l23);
                AH[aw[s]] = h01; AH[aw[s] + 4] = h23;
                AL[aw[s]] = l01; AL[aw[s] + 4] = l23;
                split_pack_bf16(pb[s].x, pb[s].y, h01, l01);
                split_pack_bf16(pb[s].z, pb[s].w, h23, l23);
                BH[bw2[s]] = h01; BH[bw2[s] + 2] = h23;
                BL[bw2[s]] = l01; BL[bw2[s] + 2] = l23;
            }
        }
        __syncthreads();
    }

    // epilogue: fragment -> gmem with bias
#pragma unroll
    for (int mt = 0; mt < 2; mt++) {
        const int r0 = bm + wm * 32 + mt * 16 + g;
#pragma unroll
        for (int nt = 0; nt < 8; nt++) {
            const int c0 = bn + wn * 64 + nt * 8 + t4 * 2;
            const float b0 = bias[c0];
            const float b1 = bias[c0 + 1];
            float2 v0, v1;
            v0.x = acc[mt][nt][0] + b0; v0.y = acc[mt][nt][1] + b1;
            v1.x = acc[mt][nt][2] + b0; v1.y = acc[mt][nt][3] + b1;
            *(float2*)(C + (size_t)r0 * N + c0) = v0;
            *(float2*)(C + (size_t)(r0 + 8) * N + c0) = v1;
        }
    }
}

// ============================================================================
// Flash attention via tf32 mma.sync (R6 proven). BQ=128, BKV=64, 2 CTAs/SM.
// ============================================================================
static constexpr int ABQ = 128, ABK = 64, APAD = 68;
static constexpr int OFF_QH = 0;
static constexpr int OFF_KH = OFF_QH + ABQ * APAD;
static constexpr int OFF_VH = OFF_KH + ABK * APAD;
static constexpr int OFF_PS = OFF_VH + ABK * APAD;
static constexpr int ATTN_SMEM = (OFF_PS + 8 * 16 * APAD) * 4;  // 104448 B

__global__ __launch_bounds__(256, 2) void attn_mma(
    const float* __restrict__ qkv, float* __restrict__ out)
{
    extern __shared__ float sm[];
    const int tid = threadIdx.x;
    const int wid = tid >> 5;
    const int lane = tid & 31;
    const int g = lane >> 2;
    const int t4 = lane & 3;
    const int qi = gridDim.x - 1 - blockIdx.x;
    const int h = blockIdx.y;
    const int b = blockIdx.z;
    const int q0 = qi * ABQ;
    const size_t rs = (size_t)3 * En;
    const float* qbase = qkv + (size_t)b * Sn * rs + (size_t)h * Dn;
    const float* kbase = qbase + En;
    const float* vbase = qbase + 2 * En;

    for (int i = tid; i < ABQ * 16; i += 256) {
        const int row = i >> 4, c4 = (i & 15) * 4;
        float4 v = *(const float4*)(qbase + (size_t)(q0 + row) * rs + c4);
        float4 hi;
        hi.x = tf32_rna(v.x * 0.125f);
        hi.y = tf32_rna(v.y * 0.125f);
        hi.z = tf32_rna(v.z * 0.125f);
        hi.w = tf32_rna(v.w * 0.125f);
        *(float4*)&sm[OFF_QH + row * APAD + c4] = hi;
    }

    float m0 = -1e30f, m1 = -1e30f, l0 = 0.f, l1 = 0.f;
    float o[8][4];
#pragma unroll
    for (int nt = 0; nt < 8; nt++)
#pragma unroll
        for (int i = 0; i < 4; i++) o[nt][i] = 0.f;

    const int wrow = wid * 16;
    float* Pw = sm + OFF_PS + wid * (16 * APAD);
    const int ntiles = 2 * qi + 2;

    for (int jt = 0; jt < ntiles; jt++) {
        const int k0 = jt * ABK;
        __syncthreads();
        for (int i = tid; i < ABK * 16; i += 256) {
            const int row = i >> 4, c4 = (i & 15) * 4;
            float4 kv = *(const float4*)(kbase + (size_t)(k0 + row) * rs + c4);
            float4 hi;
            hi.x = tf32_rna(kv.x); hi.y = tf32_rna(kv.y);
            hi.z = tf32_rna(kv.z); hi.w = tf32_rna(kv.w);
            *(float4*)&sm[OFF_KH + row * APAD + c4] = hi;
            float4 vv = *(const float4*)(vbase + (size_t)(k0 + row) * rs + c4);
            hi.x = tf32_rna(vv.x); hi.y = tf32_rna(vv.y);
            hi.z = tf32_rna(vv.z); hi.w = tf32_rna(vv.w);
            *(float4*)&sm[OFF_VH + row * APAD + c4] = hi;
        }
        __syncthreads();

        float acc[8][4];
#pragma unroll
        for (int nt = 0; nt < 8; nt++)
#pragma unroll
            for (int i = 0; i < 4; i++) acc[nt][i] = 0.f;

#pragma unroll
        for (int kb = 0; kb < 8; kb++) {
            uint32_t aq[4];
            aq[0] = __float_as_uint(sm[OFF_QH + (wrow + g) * APAD + kb * 8 + t4]);
            aq[1] = __float_as_uint(sm[OFF_QH + (wrow + g + 8) * APAD + kb * 8 + t4]);
            aq[2] = __float_as_uint(sm[OFF_QH + (wrow + g) * APAD + kb * 8 + t4 + 4]);
            aq[3] = __float_as_uint(sm[OFF_QH + (wrow + g + 8) * APAD + kb * 8 + t4 + 4]);
#pragma unroll
            for (int nt = 0; nt < 8; nt++) {
                uint32_t bh[2];
                bh[0] = __float_as_uint(sm[OFF_KH + (nt * 8 + g) * APAD + kb * 8 + t4]);
                bh[1] = __float_as_uint(sm[OFF_KH + (nt * 8 + g) * APAD + kb * 8 + t4 + 4]);
                mma_tf32(acc[nt], aq, bh);
            }
        }

        if (jt >= ntiles - 2) {
            const int r0g = q0 + wrow + g;
            const int r1g = r0g + 8;
#pragma unroll
            for (int nt = 0; nt < 8; nt++) {
                const int c = k0 + nt * 8 + t4 * 2;
                if (c > r0g)     acc[nt][0] = -1e30f;
                if (c + 1 > r0g) acc[nt][1] = -1e30f;
                if (c > r1g)     acc[nt][2] = -1e30f;
                if (c + 1 > r1g) acc[nt][3] = -1e30f;
            }
        }

        float mx0 = -1e30f, mx1 = -1e30f;
#pragma unroll
        for (int nt = 0; nt < 8; nt++) {
            mx0 = fmaxf(mx0, fmaxf(acc[nt][0], acc[nt][1]));
            mx1 = fmaxf(mx1, fmaxf(acc[nt][2], acc[nt][3]));
        }
        mx0 = fmaxf(mx0, __shfl_xor_sync(0xffffffffu, mx0, 1));
        mx0 = fmaxf(mx0, __shfl_xor_sync(0xffffffffu, mx0, 2));
        mx1 = fmaxf(mx1, __shfl_xor_sync(0xffffffffu, mx1, 1));
        mx1 = fmaxf(mx1, __shfl_xor_sync(0xffffffffu, mx1, 2));
        const float mn0 = fmaxf(m0, mx0);
        const float mn1 = fmaxf(m1, mx1);
        const float a0 = __expf(m0 - mn0);
        const float a1 = __expf(m1 - mn1);
        m0 = mn0; m1 = mn1;
        float s0 = 0.f, s1 = 0.f;
#pragma unroll
        for (int nt = 0; nt < 8; nt++) {
            acc[nt][0] = __expf(acc[nt][0] - m0); s0 += acc[nt][0];
            acc[nt][1] = __expf(acc[nt][1] - m0); s0 += acc[nt][1];
            acc[nt][2] = __expf(acc[nt][2] - m1); s1 += acc[nt][2];
            acc[nt][3] = __expf(acc[nt][3] - m1); s1 += acc[nt][3];
        }
        s0 += __shfl_xor_sync(0xffffffffu, s0, 1);
        s0 += __shfl_xor_sync(0xffffffffu, s0, 2);
        s1 += __shfl_xor_sync(0xffffffffu, s1, 1);
        s1 += __shfl_xor_sync(0xffffffffu, s1, 2);
        l0 = l0 * a0 + s0;
        l1 = l1 * a1 + s1;

#pragma unroll
        for (int nt = 0; nt < 8; nt++) {
            Pw[g * APAD + nt * 8 + t4 * 2]           = tf32_rna(acc[nt][0]);
            Pw[g * APAD + nt * 8 + t4 * 2 + 1]       = tf32_rna(acc[nt][1]);
            Pw[(g + 8) * APAD + nt * 8 + t4 * 2]     = tf32_rna(acc[nt][2]);
            Pw[(g + 8) * APAD + nt * 8 + t4 * 2 + 1] = tf32_rna(acc[nt][3]);
        }
        __syncwarp();

#pragma unroll
        for (int nt = 0; nt < 8; nt++) {
            o[nt][0] *= a0; o[nt][1] *= a0;
            o[nt][2] *= a1; o[nt][3] *= a1;
        }

#pragma unroll
        for (int kb = 0; kb < 8; kb++) {
            uint32_t ap[4];
            ap[0] = __float_as_uint(Pw[g * APAD + kb * 8 + t4]);
            ap[1] = __float_as_uint(Pw[(g + 8) * APAD + kb * 8 + t4]);
            ap[2] = __float_as_uint(Pw[g * APAD + kb * 8 + t4 + 4]);
            ap[3] = __float_as_uint(Pw[(g + 8) * APAD + kb * 8 + t4 + 4]);
#pragma unroll
            for (int nt = 0; nt < 8; nt++) {
                uint32_t bh[2];
                bh[0] = __float_as_uint(sm[OFF_VH + (kb * 8 + t4) * APAD + nt * 8 + g]);
                bh[1] = __float_as_uint(sm[OFF_VH + (kb * 8 + t4 + 4) * APAD + nt * 8 + g]);
                mma_tf32(o[nt], ap, bh);
            }
        }
        __syncwarp();
    }

    const float i0 = 1.f / l0;
    const float i1 = 1.f / l1;
    const int r0g = q0 + wrow + g;
#pragma unroll
    for (int nt = 0; nt < 8; nt++) {
        const int col = h * Dn + nt * 8 + t4 * 2;
        float2 v0, v1;
        v0.x = o[nt][0] * i0; v0.y = o[nt][1] * i0;
        v1.x = o[nt][2] * i1; v1.y = o[nt][3] * i1;
        *(float2*)(out + ((size_t)b * Sn + r0g) * En + col) = v0;
        *(float2*)(out + ((size_t)b * Sn + r0g + 8) * En + col) = v1;
    }
}

// ----------------------------------------------------------------------------
extern "C" void kernel_launch(void* const* d_in, const int* in_sizes, int n_in,
                              void* d_out, int out_size)
{
    const float* x     = (const float*)d_in[0];
    const float* w_in  = (const float*)d_in[1];
    const float* b_in  = (const float*)d_in[2];
    const float* w_out = (const float*)d_in[3];
    const float* b_out = (const float*)d_in[4];
    float* out = (float*)d_out;

    float* qkv = nullptr;
    float* attn = nullptr;
    cudaGetSymbolAddress((void**)&qkv, g_qkv);
    cudaGetSymbolAddress((void**)&attn, g_attn);

    const int M = Bn * Sn;  // 8192

    static bool attr_set = false;
    if (!attr_set) {
        cudaFuncSetAttribute(gemm_mma_bf16, cudaFuncAttributeMaxDynamicSharedMemorySize,
                             GEMM_SMEM);
        cudaFuncSetAttribute(attn_mma, cudaFuncAttributeMaxDynamicSharedMemorySize,
                             ATTN_SMEM);
        attr_set = true;
    }

    // 1) QKV projection (3xBF16 tensor cores)
    {
        dim3 grid((3 * En) / GBN, M / GBM);
        gemm_mma_bf16<<<grid, 256, GEMM_SMEM>>>(x, w_in, b_in, qkv, M, 3 * En, En);
    }

    // 2) Causal flash attention (tf32 tensor cores, 2 CTAs/SM)
    {
        dim3 grid(Sn / ABQ, Hn, Bn);
        attn_mma<<<grid, 256, ATTN_SMEM>>>(qkv, attn);
    }

    // 3) Output projection (3xBF16 tensor cores)
    {
        dim3 grid(En / GBN, M / GBM);
        gemm_mma_bf16<<<grid, 256, GEMM_SMEM>>>(attn, w_out, b_out, out, M, En, En);
    }
}